// round 3
// baseline (speedup 1.0000x reference)
#include <cuda_runtime.h>

// Soft Smith-Waterman, log-domain anti-diagonal wavefront.
// One CTA per batch. Three rotating diagonal buffers in SMEM, one
// __syncthreads per diagonal. Buffers indexed by row i (1..M); entry of
// buffer "d-1" at row i holds H[i][d-1-i].
//
// Recurrence (t=1, gap=-1):
//   a = H[i-1][j-1] + s[i][j]
//   b = H[i-1][j]   - 1
//   c = H[i][j-1]   - 1
//   m = max(a, b, c, 0)
//   H = m + log(exp(-m) + exp(a-m) + exp(b-m) + exp(c-m))   (sum >= 1)
// Answer per batch: max(H) over all cells (boundary zeros covered by init 0).

#define MM 2048
#define NN 2048
#define TPB 1024

__global__ __launch_bounds__(TPB, 1) void soft_sw_kernel(
    const float* __restrict__ S, float* __restrict__ out)
{
    __shared__ float buf0[MM + 1];
    __shared__ float buf1[MM + 1];
    __shared__ float buf2[MM + 1];
    __shared__ float red[TPB / 32];

    const int b = blockIdx.x;
    const float* __restrict__ s = S + (size_t)b * MM * NN;
    const int tid = threadIdx.x;

    // Zero all buffers: covers the H[0][*] / H[*][0] = 0 boundary and any
    // entry read before it is first written.
    for (int r = tid; r <= MM; r += TPB) {
        buf0[r] = 0.f; buf1[r] = 0.f; buf2[r] = 0.f;
    }
    __syncthreads();

    float vmax = 0.f;  // H >= 0 everywhere, and boundary is 0, so init 0 is exact.

    float* pm2 = buf0;  // diagonal d-2
    float* pm1 = buf1;  // diagonal d-1
    float* p0  = buf2;  // diagonal d (being written)

    for (int d = 2; d <= MM + NN; ++d) {
        int ilo = d - NN; if (ilo < 1) ilo = 1;
        int ihi = d - 1;  if (ihi > MM) ihi = MM;

        #pragma unroll
        for (int rr = 0; rr < 2; ++rr) {
            int i = ilo + tid + rr * TPB;
            if (i <= ihi) {
                int j = d - i;                       // 1..NN
                float sval = __ldg(&s[(size_t)(i - 1) * NN + (j - 1)]);
                float up   = (i == 1) ? 0.f : pm1[i - 1];           // H[i-1][j]
                float left = (j == 1) ? 0.f : pm1[i];               // H[i][j-1]
                float dg   = (i == 1 || j == 1) ? 0.f : pm2[i - 1]; // H[i-1][j-1]

                float a  = dg + sval;
                float bb = up - 1.0f;
                float c  = left - 1.0f;
                float m  = fmaxf(fmaxf(a, bb), fmaxf(c, 0.f));
                // All exp args <= 0; the max term contributes exactly 1, so sum >= 1.
                float sum = __expf(0.f - m) + __expf(a - m)
                          + __expf(bb - m) + __expf(c - m);
                float h = m + __logf(sum);
                p0[i] = h;
                vmax = fmaxf(vmax, h);
            }
        }
        __syncthreads();
        // Rotate: buffer that held d-2 (read-only this step) becomes the
        // write target for d+1 — the barrier above orders that correctly.
        float* t = pm2; pm2 = pm1; pm1 = p0; p0 = t;
    }

    // Block max reduction (32 warps exactly).
    #pragma unroll
    for (int o = 16; o; o >>= 1)
        vmax = fmaxf(vmax, __shfl_xor_sync(0xffffffffu, vmax, o));
    const int lane = tid & 31, wid = tid >> 5;
    if (lane == 0) red[wid] = vmax;
    __syncthreads();
    if (wid == 0) {
        float v = red[lane];
        #pragma unroll
        for (int o = 16; o; o >>= 1)
            v = fmaxf(v, __shfl_xor_sync(0xffffffffu, v, o));
        if (lane == 0) out[b] = v;
    }
}

extern "C" void kernel_launch(void* const* d_in, const int* in_sizes, int n_in,
                              void* d_out, int out_size)
{
    (void)n_in; (void)in_sizes;
    const float* S = (const float*)d_in[0];
    float* out = (float*)d_out;
    const int B = out_size;  // one scalar output per batch (expect 8)
    soft_sw_kernel<<<B, TPB>>>(S, out);
}

// round 4
// speedup vs baseline: 2.2857x; 2.2857x over previous
#include <cuda_runtime.h>
#include <cstdint>

// Soft Smith-Waterman, warp-striped pipelined wavefront.
//
// One 32-thread CTA per (batch, column-band of 32). Lane l owns column
// c = 32*w + l and walks a staircase: at step s it computes cell
// (row = s - l, col = c). Dependencies:
//   left (r, c-1)  = lane l-1's h_cur from previous step (shfl_up)
//   diag (r-1,c-1) = lane l-1's h_prev (two steps ago)   (shfl_up)
//   up   (r-1, c)  = own h_cur
// Band w>0's lane 0 gets left/diag from band w-1's right-edge column,
// streamed through global memory with release/acquire flags every 8 rows.
// All H values are kept in base-2 log domain (H * log2(e)).

#define MM 2048
#define NN 2048
#define BANDW 32
#define NBANDS (NN / BANDW)          // 64
#define NTILES (MM / 32)             // 64 score tiles per band
#define CHUNK 8                      // edge sync granularity (rows)
#define LOG2E 1.4426950408889634f
#define LN2   0.6931471805599453f

__device__ int   g_flag[8][NBANDS];
__device__ float g_edge[8][NBANDS][MM];
__device__ int   g_max[8];

static __device__ __forceinline__ float ex2f(float x) {
    float r; asm("ex2.approx.f32 %0, %1;" : "=f"(r) : "f"(x)); return r;
}
static __device__ __forceinline__ float lg2f(float x) {
    float r; asm("lg2.approx.f32 %0, %1;" : "=f"(r) : "f"(x)); return r;
}
static __device__ __forceinline__ int ld_acq(const int* p) {
    int v; asm volatile("ld.global.acquire.gpu.b32 %0, [%1];" : "=r"(v) : "l"(p)); return v;
}
static __device__ __forceinline__ void st_rel(int* p, int v) {
    asm volatile("st.global.release.gpu.b32 [%0], %1;" :: "l"(p), "r"(v) : "memory");
}
static __device__ __forceinline__ void cp16(uint32_t dst, const void* src) {
    asm volatile("cp.async.cg.shared.global [%0], [%1], 16;" :: "r"(dst), "l"(src));
}
static __device__ __forceinline__ void cp_commit() {
    asm volatile("cp.async.commit_group;");
}
template <int N> static __device__ __forceinline__ void cp_wait() {
    asm volatile("cp.async.wait_group %0;" :: "n"(N));
}

__global__ void sw_init_kernel() {
    int i = threadIdx.x;
    if (i < 8 * NBANDS) ((int*)g_flag)[i] = 0;
    if (i < 8) g_max[i] = 0;  // bits of 0.0f; H >= 0 and boundary max is 0
}

__global__ void __launch_bounds__(32, 1) sw_wave_kernel(const float* __restrict__ S) {
    __shared__ float stile[4][32][32];   // 4-slot ring of 32x32 score tiles

    const int b = blockIdx.y;
    const int w = blockIdx.x;
    const int l = threadIdx.x;
    const float* __restrict__ Sb = S + (size_t)b * MM * NN + w * BANDW;

    const float g2 = -LOG2E;             // gap penalty in base-2 domain
    float h_cur = 0.f, h_prev = 0.f;
    float b2 = g2;                       // up + gap, maintained incrementally
    float vmax = 0.f;
    float lb_carry = 0.f;                // lane0: E[r-1] (diag boundary)
    float e_cur = 0.f, e_nxt = 0.f;
    int   have_nxt = 0, flag_seen = 0;

    const int*   flagp = (w > 0) ? &g_flag[b][w - 1] : (const int*)0;
    const float* edgep = (w > 0) ? g_edge[b][w - 1] : (const float*)0;
    float* myedge = g_edge[b][w];
    int*   myflag = &g_flag[b][w];
    const bool produce = (w < NBANDS - 1);

    // Preload score tile 0 (rows 0..31 of this band); lane l copies row l.
    {
        uint32_t d = (uint32_t)__cvta_generic_to_shared(&stile[0][l][0]);
        const char* src = (const char*)(Sb + (size_t)l * NN);
        #pragma unroll
        for (int j = 0; j < 8; ++j) cp16(d + j * 16, src + j * 16);
        cp_commit();
    }

    // Initial boundary chunk (rows 0..7 of left edge) for consumer bands.
    if (w > 0) {
        int f;
        do { f = ld_acq(flagp); } while (f < 1);
        flag_seen = f;
        e_cur = (l < CHUNK) ? edgep[l] : 0.f;
    }

    for (int t = 0; t < NTILES + 1; ++t) {
        // Prefetch tile t+1 into ring slot (t+1)&3; ensure tile t resident.
        if (t + 1 < NTILES) {
            const int tt = t + 1;
            uint32_t d = (uint32_t)__cvta_generic_to_shared(&stile[tt & 3][l][0]);
            const char* src = (const char*)(Sb + (size_t)(tt * 32 + l) * NN);
            #pragma unroll
            for (int j = 0; j < 8; ++j) cp16(d + j * 16, src + j * 16);
            cp_commit();
            cp_wait<1>();
        } else {
            cp_wait<0>();
        }
        __syncwarp();

        #pragma unroll 1
        for (int c8 = 0; c8 < 4; ++c8) {
            const int s0 = t * 32 + c8 * CHUNK;

            // Boundary chunk management (uniform across warp).
            if (w > 0 && s0 < MM) {
                if (s0 > 0) {
                    const int u = s0 >> 3;          // chunk covering rows [s0, s0+7]
                    if (have_nxt) {
                        e_cur = e_nxt; have_nxt = 0;
                    } else {
                        int f = flag_seen;
                        while (f < u + 1) f = ld_acq(flagp);
                        flag_seen = f;
                        e_cur = (l < CHUNK) ? edgep[s0 + l] : 0.f;
                    }
                }
                // Prefetch next chunk when producer already published it.
                if (s0 + CHUNK < MM) {
                    const int un = (s0 >> 3) + 1;
                    if (flag_seen < un + 1) flag_seen = ld_acq(flagp);
                    if (flag_seen >= un + 1) {
                        e_nxt = (l < CHUNK) ? edgep[s0 + CHUNK + l] : 0.f;
                        have_nxt = 1;
                    }
                }
            }

            #pragma unroll
            for (int k = 0; k < CHUNK; ++k) {
                const int s = s0 + k;
                const int r = s - l;
                const bool valid = (r >= 0) && (r < MM);

                float sv = 0.f;
                if (valid) sv = stile[(r >> 5) & 3][r & 31][l] * LOG2E;

                float lw = __shfl_up_sync(0xffffffffu, h_cur, 1);
                float dg = __shfl_up_sync(0xffffffffu, h_prev, 1);
                float bv = __shfl_sync(0xffffffffu, e_cur, k);
                if (l == 0) { lw = bv; dg = lb_carry; lb_carry = bv; }

                if (valid) {
                    float a2 = dg + sv;         // diag + score
                    float c2 = lw + g2;         // left + gap
                    float m  = fmaxf(fmaxf(a2, c2), fmaxf(b2, 0.f));
                    float sum = ex2f(0.f - m) + ex2f(a2 - m)
                              + ex2f(b2 - m) + ex2f(c2 - m);
                    float h = m + lg2f(sum);
                    h_prev = h_cur;
                    h_cur  = h;
                    b2     = h + g2;            // next step's up+gap
                    vmax   = fmaxf(vmax, h);
                    if (l == 31 && produce) myedge[r] = h;
                }
                if (l == 31 && produce && r >= 0 && (r & 7) == 7) {
                    st_rel(myflag, (r + 1) >> 3);
                }
            }
        }
    }

    // Warp max reduction, convert back from base-2 domain, publish.
    #pragma unroll
    for (int o = 16; o; o >>= 1)
        vmax = fmaxf(vmax, __shfl_xor_sync(0xffffffffu, vmax, o));
    if (l == 0) atomicMax(&g_max[b], __float_as_int(vmax * LN2));
}

__global__ void sw_final_kernel(float* __restrict__ out, int n) {
    int i = threadIdx.x;
    if (i < n) out[i] = __int_as_float(g_max[i]);
}

extern "C" void kernel_launch(void* const* d_in, const int* in_sizes, int n_in,
                              void* d_out, int out_size) {
    (void)n_in; (void)in_sizes;
    const float* S = (const float*)d_in[0];
    float* out = (float*)d_out;
    const int B = out_size;  // 8

    sw_init_kernel<<<1, 1024>>>();
    dim3 grid(NBANDS, B);
    sw_wave_kernel<<<grid, 32>>>(S);
    sw_final_kernel<<<1, 32>>>(out, B);
}

// round 5
// speedup vs baseline: 5.4741x; 2.3949x over previous
#include <cuda_runtime.h>
#include <cstdint>

// Soft Smith-Waterman in LINEAR (exp) domain.
// X = exp(H) obeys:  X = 1 + e^s * Xdiag + e^-1 * (Xup + Xleft)   (linear!)
// Carry Y = X * 2^-K with warp-uniform K, renormalized every 32 rows.
// Layout: 4 cols/lane, 128-col bands, 16 bands/batch, 2-row lane stagger.
// Band edges exchanged through global memory in log2 domain with
// release/acquire flags every 8 rows.

#define MM 2048
#define NN 2048
#define COLS 4
#define BANDW (32 * COLS)       // 128
#define NBANDS (NN / BANDW)     // 16
#define CHUNK 8
#define RING 4                  // score ring: chunk slots
#define PF 3                    // prefetch distance in chunks (24 steps)
#define TOTCH 264               // ceil((2048 + 62)/8) = 264 chunks
#define LOG2E 1.4426950408889634f
#define LN2   0.6931471805599453f
#define EG    0.36787944117144233f   // e^-1

__device__ int   g_flag[8][NBANDS];
__device__ float g_edge[8][NBANDS][MM];
__device__ int   g_max[8];

static __device__ __forceinline__ float ex2f(float x) {
    float r; asm("ex2.approx.f32 %0, %1;" : "=f"(r) : "f"(x)); return r;
}
static __device__ __forceinline__ float lg2f(float x) {
    float r; asm("lg2.approx.f32 %0, %1;" : "=f"(r) : "f"(x)); return r;
}
static __device__ __forceinline__ int ld_acq(const int* p) {
    int v; asm volatile("ld.global.acquire.gpu.b32 %0, [%1];" : "=r"(v) : "l"(p)); return v;
}
static __device__ __forceinline__ void st_rel(int* p, int v) {
    asm volatile("st.global.release.gpu.b32 [%0], %1;" :: "l"(p), "r"(v) : "memory");
}
static __device__ __forceinline__ void cp16(uint32_t dst, const void* src) {
    asm volatile("cp.async.cg.shared.global [%0], [%1], 16;" :: "r"(dst), "l"(src));
}
static __device__ __forceinline__ void cp_commit() {
    asm volatile("cp.async.commit_group;");
}
template <int N> static __device__ __forceinline__ void cp_wait() {
    asm volatile("cp.async.wait_group %0;" :: "n"(N));
}

__global__ void sw_init_kernel() {
    int i = threadIdx.x;
    if (i < 8 * NBANDS) ((int*)g_flag)[i] = 0;
    if (i < 8) g_max[i] = 0;   // bits of 0.0f; H >= 0 so this is the boundary max
}

__global__ void __launch_bounds__(32, 1) sw_wave_kernel(const float* __restrict__ S) {
    __shared__ float4 stile[RING][CHUNK][32];

    const int b = blockIdx.y;
    const int w = blockIdx.x;
    const int l = threadIdx.x;
    // Lane l owns columns w*128 + 4l .. +3; its row r score quad is at Sb + r*NN.
    const float* __restrict__ Sb =
        S + (size_t)b * MM * NN + (size_t)w * BANDW + (size_t)l * COLS;

    const int*   flagp  = (w > 0) ? &g_flag[b][w - 1] : (const int*)0;
    const float* edgep  = (w > 0) ? g_edge[b][w - 1] : (const float*)0;
    float*       myedge = g_edge[b][w];
    int*         myflag = &g_flag[b][w];
    const bool   produce = (w != NBANDS - 1);

    // State (all Y values share the warp-uniform scale 2^-K, K tracked in Kf)
    float Yp0 = 0.f, Yp1 = 0.f, Yp2 = 0.f, Yp3 = 0.f;  // previous row of my 4 cols
    float y1 = 0.f, y2 = 0.f, y3 = 0.f;                  // my last-col Y, steps t-1..t-3
    float pl = 0.f, pd = 0.f;                            // prefetched neighbor left/diag
    float pbv = 0.f;                                     // lane0: edge value of prev row
    float econv = 0.f;                                   // converted edge chunk value
    float C = 1.0f;                                      // scaled "+1" restart term = 2^-K
    float Kf = 0.f;                                      // current K (log2 units)
    float Ymax = 0.f;                                    // running max Y this renorm period
    float vh = 0.f;                                      // best H so far, log2 units
    int   flag_seen = 0;

    // Prologue: prefetch score chunks 0..PF-1 (steps 0..23)
    #pragma unroll
    for (int pc = 0; pc < PF; ++pc) {
        #pragma unroll
        for (int j = 0; j < CHUNK; ++j) {
            int r = pc * CHUNK + j - 2 * l;
            if (r >= 0 && r < MM) {
                uint32_t d = (uint32_t)__cvta_generic_to_shared(&stile[pc][j][l]);
                cp16(d, Sb + (size_t)r * NN);
            }
        }
        cp_commit();
    }

    for (int c = 0; c < TOTCH; ++c) {
        const int t0 = c * CHUNK;

        // ---- Renormalize every 32 rows (4 chunks) ----
        if ((c & 3) == 0 && c > 0) {
            float m = fmaxf(fmaxf(Yp0, Yp1), fmaxf(Yp2, Yp3));
            #pragma unroll
            for (int o = 16; o; o >>= 1)
                m = fmaxf(m, __shfl_xor_sync(0xffffffffu, m, o));
            int k = (__float_as_int(m) >> 23) - 127;        // ilogb(m), m>0 normal
            float sc = __int_as_float((127 - k) << 23);     // exact 2^-k
            vh = fmaxf(vh, lg2f(Ymax) + Kf);                // flush period max (old K)
            Ymax = 0.f;
            Kf += (float)k;
            C *= sc;
            Yp0 *= sc; Yp1 *= sc; Yp2 *= sc; Yp3 *= sc;
            y1 *= sc;  y2 *= sc;  y3 *= sc;
            pl *= sc;  pd *= sc;  pbv *= sc;  econv *= sc;
        }

        // ---- Consumer: fetch + convert left-edge chunk (rows t0..t0+7) ----
        if (w > 0 && t0 < MM) {
            const int need = c + 1;
            if (flag_seen < need) {
                int f; do { f = ld_acq(flagp); } while (f < need);
                flag_seen = f;
            }
            float eh = (l < CHUNK) ? edgep[t0 + l] : 0.f;
            econv = ex2f(eh - Kf);      // into current scale
        }

        // ---- Issue score chunk c+PF, wait for chunk c ----
        if (c + PF < TOTCH) {
            #pragma unroll
            for (int j = 0; j < CHUNK; ++j) {
                int r = (c + PF) * CHUNK + j - 2 * l;
                if (r >= 0 && r < MM) {
                    uint32_t d = (uint32_t)__cvta_generic_to_shared(
                        &stile[(c + PF) & (RING - 1)][j][l]);
                    cp16(d, Sb + (size_t)r * NN);
                }
            }
            cp_commit();
        }
        cp_wait<PF - 1>();

        // ---- 8 steps, one row per lane per step (stagger 2) ----
        #pragma unroll
        for (int j = 0; j < CHUNK; ++j) {
            const int t = t0 + j;
            const int r = t - 2 * l;

            float4 s4 = stile[c & (RING - 1)][j][l];

            // Prefetch next step's neighbor values (inputs finalized >= 1 step ago,
            // results consumed next step -> full shfl latency hidden).
            float npl = __shfl_up_sync(0xffffffffu, y1, 1);
            float npd = __shfl_up_sync(0xffffffffu, y2, 1);
            float bv  = __shfl_sync(0xffffffffu, econv, j);

            float left = pl, diag = pd;
            if (l == 0) {
                left = (w == 0) ? C : bv;   // column -1 boundary or converted edge
                diag = pbv;                 // edge value of previous row
                pbv  = left;
            }
            if (r == 0) {                   // virtual row -1 is the zero boundary: X=1
                diag = C;
                Yp0 = C; Yp1 = C; Yp2 = C; Yp3 = C;
            }

            float ynew = 0.f;
            if (r >= 0 && r < MM) {
                float es0 = ex2f(s4.x * LOG2E);
                float es1 = ex2f(s4.y * LOG2E);
                float es2 = ex2f(s4.z * LOG2E);
                float es3 = ex2f(s4.w * LOG2E);
                float c0 = fmaf(EG, left, fmaf(EG, Yp0, fmaf(es0, diag, C)));
                float c1 = fmaf(EG, c0,   fmaf(EG, Yp1, fmaf(es1, Yp0, C)));
                float c2 = fmaf(EG, c1,   fmaf(EG, Yp2, fmaf(es2, Yp1, C)));
                float c3 = fmaf(EG, c2,   fmaf(EG, Yp3, fmaf(es3, Yp2, C)));
                Ymax = fmaxf(Ymax, fmaxf(fmaxf(c0, c1), fmaxf(c2, c3)));
                Yp0 = c0; Yp1 = c1; Yp2 = c2; Yp3 = c3;
                ynew = c3;
                if (l == 31 && produce) {
                    myedge[r] = lg2f(c3) + Kf;          // edge in log2 domain
                    if ((r & 7) == 7) st_rel(myflag, (r + 1) >> 3);
                }
            }
            y3 = y2; y2 = y1; y1 = ynew;
            pl = npl; pd = npd;
        }
    }

    // Flush last period's max, reduce, publish (H = log2-max * ln2, H >= 0).
    vh = fmaxf(vh, lg2f(Ymax) + Kf);
    float hv = vh * LN2;
    #pragma unroll
    for (int o = 16; o; o >>= 1)
        hv = fmaxf(hv, __shfl_xor_sync(0xffffffffu, hv, o));
    if (l == 0) atomicMax(&g_max[b], __float_as_int(fmaxf(hv, 0.f)));
}

__global__ void sw_final_kernel(float* __restrict__ out, int n) {
    int i = threadIdx.x;
    if (i < n) out[i] = __int_as_float(g_max[i]);
}

extern "C" void kernel_launch(void* const* d_in, const int* in_sizes, int n_in,
                              void* d_out, int out_size) {
    (void)n_in; (void)in_sizes;
    const float* S = (const float*)d_in[0];
    float* out = (float*)d_out;
    const int B = out_size;   // 8

    sw_init_kernel<<<1, 256>>>();
    dim3 grid(NBANDS, B);
    sw_wave_kernel<<<grid, 32>>>(S);
    sw_final_kernel<<<1, 32>>>(out, B);
}

// round 6
// speedup vs baseline: 5.5450x; 1.0129x over previous
#include <cuda_runtime.h>
#include <cstdint>

// Soft Smith-Waterman in LINEAR (exp) domain, branchless pipelined wavefront.
// X = exp(H):  X = 1 + e^s * Xdiag + e^-1 * (Xup + Xleft)
// Carry Y = X * 2^-K (warp-uniform int K), renorm every 32 rows.
// 4 cols/lane, 128-col bands, 16 bands/batch, 2-row lane stagger.
// Band edges passed LINEAR with per-row K through global memory (L2-only via
// __ldcg / release-acquire flags once per 8-row chunk).

#define MM 2048
#define NN 2048
#define COLS 4
#define BANDW (32 * COLS)        // 128
#define NBANDS (NN / BANDW)      // 16
#define CHUNK 8
#define RING 8
#define PF 4
#define TOTCH 264                // ceil((2048 + 62 + 1)/8)
#define LOG2E 1.4426950408889634f
#define LN2   0.6931471805599453f
#define EG    0.36787944117144233f   // e^-1

__device__ int   g_flag[8][NBANDS];
__device__ float g_edge[8][NBANDS][MM];
__device__ int   g_edgeK[8][NBANDS][MM];
__device__ int   g_max[8];

static __device__ __forceinline__ float ex2f(float x) {
    float r; asm("ex2.approx.f32 %0, %1;" : "=f"(r) : "f"(x)); return r;
}
static __device__ __forceinline__ float lg2f(float x) {
    float r; asm("lg2.approx.f32 %0, %1;" : "=f"(r) : "f"(x)); return r;
}
static __device__ __forceinline__ int ld_acq(const int* p) {
    int v; asm volatile("ld.global.acquire.gpu.b32 %0, [%1];" : "=r"(v) : "l"(p)); return v;
}
static __device__ __forceinline__ void st_rel(int* p, int v) {
    asm volatile("st.global.release.gpu.b32 [%0], %1;" :: "l"(p), "r"(v) : "memory");
}
static __device__ __forceinline__ void cp16(uint32_t dst, const void* src) {
    asm volatile("cp.async.cg.shared.global [%0], [%1], 16;" :: "r"(dst), "l"(src));
}
static __device__ __forceinline__ void cp_commit() {
    asm volatile("cp.async.commit_group;");
}
template <int N> static __device__ __forceinline__ void cp_wait() {
    asm volatile("cp.async.wait_group %0;" :: "n"(N));
}

__global__ void sw_init_kernel() {
    int i = threadIdx.x;
    if (i < 8 * NBANDS) ((int*)g_flag)[i] = 0;
    if (i < 8) g_max[i] = 0;   // bits of 0.0f; H >= 0
}

__global__ void __launch_bounds__(32, 1) sw_wave_kernel(const float* __restrict__ S) {
    __shared__ float4 stile[RING][CHUNK][32];

    const int b = blockIdx.y;
    const int w = blockIdx.x;
    const int l = threadIdx.x;
    const float* __restrict__ Sb =
        S + (size_t)b * MM * NN + (size_t)w * BANDW + (size_t)l * COLS;

    const int*   flagp   = (w > 0) ? &g_flag[b][w - 1]  : (const int*)0;
    const float* edgep   = (w > 0) ? g_edge[b][w - 1]   : (const float*)0;
    const int*   edgeKp  = (w > 0) ? g_edgeK[b][w - 1]  : (const int*)0;
    float*       myedge  = g_edge[b][w];
    int*         myedgeK = g_edgeK[b][w];
    int*         myflag  = &g_flag[b][w];
    const bool   produce = (w != NBANDS - 1);

    // Zero smem ring so any discarded garbage read stays finite.
    #pragma unroll
    for (int sl = 0; sl < RING; ++sl)
        #pragma unroll
        for (int j = 0; j < CHUNK; ++j)
            stile[sl][j][l] = make_float4(0.f, 0.f, 0.f, 0.f);

    // DP state
    float Yp0 = 0.f, Yp1 = 0.f, Yp2 = 0.f, Yp3 = 0.f;
    float y1 = 0.f, y2 = 0.f;        // own last-col Y, 1 and 2 steps back
    float pl = 0.f, pd = 0.f;        // prefetched neighbor left/diag
    float pbv = 0.f;                 // lane0: edge value of previous row
    float C = 1.0f;                  // scaled restart term = 2^-K
    int   Ki = 0;
    float Ymax = 0.f, vh = 0.f;      // period max; best H (log2 units)
    float e0=0,e1=0,e2=0,e3=0,e4=0,e5=0,e6=0,e7=0;   // converted edge chunk
    float4 rYa = {0,0,0,0}, rYb = {0,0,0,0};          // raw edge prefetch
    int4   rKa = {0,0,0,0}, rKb = {0,0,0,0};
    int   flag_seen = 0, f_pend = 0;
    bool  have_raw = false;

    // Prologue: prefetch score chunks 0..PF-1.
    #pragma unroll
    for (int pc = 0; pc < PF; ++pc) {
        #pragma unroll
        for (int j = 0; j < CHUNK; ++j) {
            int r = pc * CHUNK + j - 2 * l;
            if (r >= 0 && r < MM) {
                uint32_t d = (uint32_t)__cvta_generic_to_shared(&stile[pc][j][l]);
                cp16(d, Sb + (size_t)r * NN);
            }
        }
        cp_commit();
    }

#define CONVK(Y, KK) ((Y) * __int_as_float((127 + max(-126, min(127, (KK) - Ki))) << 23))

#define STEP_FAST(jj, EJ) { \
    float4 s4 = stile[c & (RING - 1)][jj][l]; \
    float npl = __shfl_up_sync(0xffffffffu, y1, 1); \
    float npd = __shfl_up_sync(0xffffffffu, y2, 1); \
    float left = (l == 0) ? (EJ) : pl; \
    float diag = (l == 0) ? pbv : pd; \
    float es0 = ex2f(s4.x * LOG2E), es1 = ex2f(s4.y * LOG2E); \
    float es2 = ex2f(s4.z * LOG2E), es3 = ex2f(s4.w * LOG2E); \
    float c0 = fmaf(EG, left, fmaf(EG, Yp0, fmaf(es0, diag, C))); \
    float c1 = fmaf(EG, c0, fmaf(EG, Yp1, fmaf(es1, Yp0, C))); \
    float c2 = fmaf(EG, c1, fmaf(EG, Yp2, fmaf(es2, Yp1, C))); \
    float c3 = fmaf(EG, c2, fmaf(EG, Yp3, fmaf(es3, Yp2, C))); \
    Ymax = fmaxf(Ymax, fmaxf(fmaxf(c0, c1), fmaxf(c2, c3))); \
    Yp0 = c0; Yp1 = c1; Yp2 = c2; Yp3 = c3; \
    if (l == 31 && produce) { int r = t0 + (jj) - 62; myedge[r] = c3; myedgeK[r] = Ki; } \
    y2 = y1; y1 = c3; pbv = (EJ); pl = npl; pd = npd; }

#define STEP_SLOW(jj, EJ) { \
    const int r = t0 + (jj) - 2 * l; \
    const bool z = (r == 0); \
    const bool valid = ((unsigned)r < (unsigned)MM); \
    float4 s4 = stile[c & (RING - 1)][jj][l]; \
    float npl = __shfl_up_sync(0xffffffffu, y1, 1); \
    float npd = __shfl_up_sync(0xffffffffu, y2, 1); \
    float left = (l == 0) ? (EJ) : pl; \
    float diag = (l == 0) ? pbv : pd; \
    diag = z ? C : diag; \
    float q0 = z ? C : Yp0, q1 = z ? C : Yp1, q2 = z ? C : Yp2, q3 = z ? C : Yp3; \
    float es0 = ex2f(s4.x * LOG2E), es1 = ex2f(s4.y * LOG2E); \
    float es2 = ex2f(s4.z * LOG2E), es3 = ex2f(s4.w * LOG2E); \
    float c0 = fmaf(EG, left, fmaf(EG, q0, fmaf(es0, diag, C))); \
    float c1 = fmaf(EG, c0, fmaf(EG, q1, fmaf(es1, q0, C))); \
    float c2 = fmaf(EG, c1, fmaf(EG, q2, fmaf(es2, q1, C))); \
    float c3 = fmaf(EG, c2, fmaf(EG, q3, fmaf(es3, q2, C))); \
    float m4 = fmaxf(fmaxf(c0, c1), fmaxf(c2, c3)); \
    Ymax = fmaxf(Ymax, valid ? m4 : 0.f); \
    Yp0 = valid ? c0 : q0; Yp1 = valid ? c1 : q1; \
    Yp2 = valid ? c2 : q2; Yp3 = valid ? c3 : q3; \
    float ynew = valid ? c3 : 0.f; \
    if (l == 31 && produce && valid) { myedge[r] = c3; myedgeK[r] = Ki; } \
    y2 = y1; y1 = ynew; pbv = (EJ); pl = npl; pd = npd; }

    for (int c = 0; c < TOTCH; ++c) {
        const int t0 = c * CHUNK;

        // ---- Renormalize every 32 rows (4 chunks) ----
        if ((c & 3) == 0 && c != 0) {
            float m = fmaxf(fmaxf(Yp0, Yp1), fmaxf(Yp2, Yp3));
            #pragma unroll
            for (int o = 16; o; o >>= 1)
                m = fmaxf(m, __shfl_xor_sync(0xffffffffu, m, o));
            int k = (__float_as_int(m) >> 23) - 127;       // ilogb(m), m >= C > 0
            float sc = __int_as_float((127 - k) << 23);
            vh = fmaxf(vh, lg2f(Ymax) + (float)Ki);        // flush with old K
            Ymax = 0.f; Ki += k; C *= sc;
            Yp0 *= sc; Yp1 *= sc; Yp2 *= sc; Yp3 *= sc;
            y1 *= sc; y2 *= sc; pl *= sc; pd *= sc; pbv *= sc;
        }

        // ---- Edge intake (pipelined; acquire consumed one chunk late) ----
        const bool need_edge = (w > 0) && (t0 < MM);
        if (need_edge) {
            flag_seen = max(flag_seen, f_pend);            // consume last chunk's acquire
            if (!have_raw) {                               // blocking fallback (rare)
                int f = flag_seen;
                while (f < c + 1) f = ld_acq(flagp);
                flag_seen = f;
                rYa = __ldcg((const float4*)(edgep + t0));
                rYb = __ldcg((const float4*)(edgep + t0 + 4));
                rKa = __ldcg((const int4*)(edgeKp + t0));
                rKb = __ldcg((const int4*)(edgeKp + t0 + 4));
            }
            // Convert raw (linear Y, per-row K) into current scale — FMUL only.
            e0 = CONVK(rYa.x, rKa.x); e1 = CONVK(rYa.y, rKa.y);
            e2 = CONVK(rYa.z, rKa.z); e3 = CONVK(rYa.w, rKa.w);
            e4 = CONVK(rYb.x, rKb.x); e5 = CONVK(rYb.y, rKb.y);
            e6 = CONVK(rYb.z, rKb.z); e7 = CONVK(rYb.w, rKb.w);
            // Prefetch next chunk's raw edge if already published.
            have_raw = false;
            if (t0 + CHUNK < MM && flag_seen >= c + 2) {
                rYa = __ldcg((const float4*)(edgep + t0 + 8));
                rYb = __ldcg((const float4*)(edgep + t0 + 12));
                rKa = __ldcg((const int4*)(edgeKp + t0 + 8));
                rKb = __ldcg((const int4*)(edgeKp + t0 + 12));
                have_raw = true;
            }
            f_pend = ld_acq(flagp);                        // consumed NEXT chunk
        } else {
            e0 = e1 = e2 = e3 = e4 = e5 = e6 = e7 = C;     // zero boundary (band 0)
        }

        // ---- Score pipeline: issue chunk c+PF, ensure chunk c resident ----
        if (c + PF < TOTCH) {
            #pragma unroll
            for (int j = 0; j < CHUNK; ++j) {
                int r = (c + PF) * CHUNK + j - 2 * l;
                if (r >= 0 && r < MM) {
                    uint32_t d = (uint32_t)__cvta_generic_to_shared(
                        &stile[(c + PF) & (RING - 1)][j][l]);
                    cp16(d, Sb + (size_t)r * NN);
                }
            }
            cp_commit();
        }
        cp_wait<PF - 1>();
        __syncwarp();

        // ---- 8 DP steps ----
        if (c >= 8 && c <= 255) {       // all lanes valid, r != 0, edges in range
            STEP_FAST(0, e0) STEP_FAST(1, e1) STEP_FAST(2, e2) STEP_FAST(3, e3)
            STEP_FAST(4, e4) STEP_FAST(5, e5) STEP_FAST(6, e6) STEP_FAST(7, e7)
        } else {
            STEP_SLOW(0, e0) STEP_SLOW(1, e1) STEP_SLOW(2, e2) STEP_SLOW(3, e3)
            STEP_SLOW(4, e4) STEP_SLOW(5, e5) STEP_SLOW(6, e6) STEP_SLOW(7, e7)
        }

        // ---- Publish flag once per chunk: groups complete = c - 7 ----
        if (l == 31 && produce && c >= 8) st_rel(myflag, c - 7);
    }

    // Final flush + warp reduce + publish (H >= 0).
    vh = fmaxf(vh, lg2f(Ymax) + (float)Ki);
    float hv = vh * LN2;
    #pragma unroll
    for (int o = 16; o; o >>= 1)
        hv = fmaxf(hv, __shfl_xor_sync(0xffffffffu, hv, o));
    if (l == 0) atomicMax(&g_max[b], __float_as_int(fmaxf(hv, 0.f)));
}

__global__ void sw_final_kernel(float* __restrict__ out, int n) {
    int i = threadIdx.x;
    if (i < n) out[i] = __int_as_float(g_max[i]);
}

extern "C" void kernel_launch(void* const* d_in, const int* in_sizes, int n_in,
                              void* d_out, int out_size) {
    (void)n_in; (void)in_sizes;
    const float* S = (const float*)d_in[0];
    float* out = (float*)d_out;
    const int B = out_size;   // 8

    sw_init_kernel<<<1, 256>>>();
    dim3 grid(NBANDS, B);
    sw_wave_kernel<<<grid, 32>>>(S);
    sw_final_kernel<<<1, 32>>>(out, B);
}